// round 3
// baseline (speedup 1.0000x reference)
#include <cuda_runtime.h>
#include <cstdint>

#define FM            31
#define A_TOTAL       8649        // 31*31*9
#define BATCH_N       64
#define PRE_TOPN      6000
#define POST_TOPN     1500
#define IOU_THR       0.7f
#define NTHREADS      1024

// Shared-memory layout (descending alignment).
struct SmemLayout {
    float4             cbox[PRE_TOPN];     // candidate boxes (y1,x1,y2,x2), unclipped
    unsigned long long ckey[PRE_TOPN];     // (score_bits<<32)|(~idx); 0 == suppressed
    unsigned long long wkey[32];           // per-warp argmax keys
    unsigned long long prefix;             // radix-select state / final threshold
    unsigned long long selkey;             // selected key this NMS step
    float4             selbox;             // (unused scratch)
    int                wpos[32];           // per-warp argmax positions
    int                hist[256];          // radix histogram
    int                kk;                 // radix-select remaining rank
    int                cnt;                // compaction counter
    int                selpos;             // selected position this NMS step
};

__device__ __forceinline__ unsigned long long make_key(float s, int i) {
    // score descending, then original index ascending (matches jax top_k + argmax ties)
    return ((unsigned long long)__float_as_uint(s) << 32)
         | (unsigned long long)(0xFFFFFFFFu - (unsigned)i);
}

extern __shared__ unsigned char smem_raw[];

__global__ void __launch_bounds__(NTHREADS, 1)
roibbox_kernel(const float* __restrict__ deltas,   // [B, A, 4]  (already *variances applied here)
               const float* __restrict__ probs,    // [B, A]
               const float* __restrict__ anchors,  // [A, 4]
               float* __restrict__ out_boxes,      // [B, 1500, 4]
               float* __restrict__ out_scores)     // [B, 1500]
{
    SmemLayout* s = (SmemLayout*)smem_raw;
    const int b    = blockIdx.x;
    const int tid  = threadIdx.x;
    const int warp = tid >> 5;
    const int lane = tid & 31;

    const float* pr = probs + (size_t)b * A_TOTAL;

    // ---------------- Phase 1: exact 6000th-largest key via byte radix-select ----------------
    if (tid == 0) { s->prefix = 0ULL; s->kk = PRE_TOPN; }
    __syncthreads();

    for (int pass = 0; pass < 8; ++pass) {
        const int shift = 56 - 8 * pass;
        for (int i = tid; i < 256; i += NTHREADS) s->hist[i] = 0;
        __syncthreads();

        const unsigned long long pref = s->prefix;
        for (int i = tid; i < A_TOTAL; i += NTHREADS) {
            unsigned long long k = make_key(pr[i], i);
            bool match = (pass == 0) || ((k >> (shift + 8)) == pref);
            if (match) atomicAdd(&s->hist[(int)((k >> shift) & 255ULL)], 1);
        }
        __syncthreads();

        if (tid == 0) {
            int kk = s->kk;
            int cum = 0, bsel = 0;
            for (int bb = 255; bb >= 0; --bb) {
                int h = s->hist[bb];
                if (cum + h >= kk) { bsel = bb; s->kk = kk - cum; break; }
                cum += h;
            }
            s->prefix = (pref << 8) | (unsigned long long)bsel;
        }
        __syncthreads();
    }
    const unsigned long long thresh = s->prefix;  // exact 6000th largest key (keys distinct)

    // ---------------- Phase 2: compact top-6000 + decode boxes into SMEM ----------------
    if (tid == 0) s->cnt = 0;
    __syncthreads();

    const float4* anc4 = (const float4*)anchors;
    const float4* del4 = (const float4*)(deltas + (size_t)b * A_TOTAL * 4);

    for (int i = tid; i < A_TOTAL; i += NTHREADS) {
        unsigned long long k = make_key(pr[i], i);
        if (k >= thresh) {
            int p = atomicAdd(&s->cnt, 1);
            float4 a = anc4[i];
            float4 d = del4[i];
            float anc_h = a.z - a.x;
            float anc_w = a.w - a.y;
            float acy   = a.x + 0.5f * anc_h;
            float acx   = a.y + 0.5f * anc_w;
            float h  = expf(d.z * 0.2f) * anc_h;
            float w  = expf(d.w * 0.2f) * anc_w;
            float cy = d.x * 0.1f * anc_h + acy;
            float cx = d.y * 0.1f * anc_w + acx;
            s->cbox[p] = make_float4(cy - 0.5f * h, cx - 0.5f * w,
                                     cy + 0.5f * h, cx + 0.5f * w);
            s->ckey[p] = k;
        }
    }
    __syncthreads();

    // ---------------- Phase 3: greedy NMS (serial picks, parallel argmax + suppression) -----
    float* ob = out_boxes  + (size_t)b * POST_TOPN * 4;
    float* os = out_scores + (size_t)b * POST_TOPN;

    int t = 0;
    for (; t < POST_TOPN; ++t) {
        // block argmax over ckey
        unsigned long long best = 0ULL;
        int bpos = -1;
        #pragma unroll 6
        for (int j = tid; j < PRE_TOPN; j += NTHREADS) {
            unsigned long long k = s->ckey[j];
            if (k > best) { best = k; bpos = j; }
        }
        #pragma unroll
        for (int off = 16; off; off >>= 1) {
            unsigned long long ok = __shfl_down_sync(0xffffffffu, best, off);
            int op               = __shfl_down_sync(0xffffffffu, bpos, off);
            if (ok > best) { best = ok; bpos = op; }
        }
        if (lane == 0) { s->wkey[warp] = best; s->wpos[warp] = bpos; }
        __syncthreads();
        if (warp == 0) {
            best = s->wkey[lane];
            bpos = s->wpos[lane];
            #pragma unroll
            for (int off = 16; off; off >>= 1) {
                unsigned long long ok = __shfl_down_sync(0xffffffffu, best, off);
                int op               = __shfl_down_sync(0xffffffffu, bpos, off);
                if (ok > best) { best = ok; bpos = op; }
            }
            if (lane == 0) { s->selkey = best; s->selpos = bpos; }
        }
        __syncthreads();

        const unsigned long long sk = s->selkey;
        if (sk == 0ULL) break;  // no active candidates remain

        const float4 sb = s->cbox[s->selpos];
        if (tid == 0) {
            ob[t * 4 + 0] = fminf(fmaxf(sb.x, 0.0f), 1.0f);
            ob[t * 4 + 1] = fminf(fmaxf(sb.y, 0.0f), 1.0f);
            ob[t * 4 + 2] = fminf(fmaxf(sb.z, 0.0f), 1.0f);
            ob[t * 4 + 3] = fminf(fmaxf(sb.w, 0.0f), 1.0f);
            os[t] = __uint_as_float((unsigned)(sk >> 32));
        }

        const float area_s = (sb.z - sb.x) * (sb.w - sb.y);
        #pragma unroll 6
        for (int j = tid; j < PRE_TOPN; j += NTHREADS) {
            unsigned long long k = s->ckey[j];
            if (k == 0ULL) continue;
            float4 bb = s->cbox[j];
            float y1 = fmaxf(sb.x, bb.x);
            float x1 = fmaxf(sb.y, bb.y);
            float y2 = fminf(sb.z, bb.z);
            float x2 = fminf(sb.w, bb.w);
            float inter  = fmaxf(y2 - y1, 0.0f) * fmaxf(x2 - x1, 0.0f);
            float area_b = (bb.z - bb.x) * (bb.w - bb.y);
            float iou = inter / (area_s + area_b - inter + 1e-9f);
            if (iou > IOU_THR) s->ckey[j] = 0ULL;
        }
        __syncthreads();
    }

    // zero-fill remaining slots (reference emits zeros once candidates are exhausted)
    for (int idx = t * 4 + tid; idx < POST_TOPN * 4; idx += NTHREADS) ob[idx] = 0.0f;
    for (int idx = t + tid;     idx < POST_TOPN;     idx += NTHREADS) os[idx] = 0.0f;
}

extern "C" void kernel_launch(void* const* d_in, const int* in_sizes, int n_in,
                              void* d_out, int out_size) {
    const float* deltas  = (const float*)d_in[0];   // [64,31,31,36] f32
    const float* probs   = (const float*)d_in[1];   // [64,31,31,9]  f32
    // d_in[2]: gt_labels int64 — unused
    const float* anchors = (const float*)d_in[3];   // [8649,4] f32

    float* out_boxes  = (float*)d_out;                                  // [64,1500,4]
    float* out_scores = (float*)d_out + (size_t)BATCH_N * POST_TOPN * 4; // [64,1500]

    const size_t smem_bytes = sizeof(SmemLayout);
    cudaFuncSetAttribute(roibbox_kernel,
                         cudaFuncAttributeMaxDynamicSharedMemorySize,
                         (int)smem_bytes);

    roibbox_kernel<<<BATCH_N, NTHREADS, smem_bytes>>>(
        deltas, probs, anchors, out_boxes, out_scores);
}

// round 6
// speedup vs baseline: 1.4068x; 1.4068x over previous
#include <cuda_runtime.h>
#include <cstdint>

#define A_TOTAL       8649        // 31*31*9
#define BATCH_N       64
#define PRE_TOPN      6000
#define POST_TOPN     1500
#define IOU_THR       0.7f
#define NT            512
#define NSLOT         12          // ceil(6000/512)
#define NWARP         16

// Shared memory: staging for compaction (phases 1-2) + reduction scratch (phase 3).
struct Smem {
    float4             cbox[PRE_TOPN];     // decoded candidate boxes (staging)
    float4             wbox[NWARP];        // per-warp argmax boxes
    float4             selbox;             // selected box this step
    unsigned long long ckey[PRE_TOPN];     // candidate keys (staging)
    unsigned long long wkey[NWARP];        // per-warp argmax keys
    unsigned long long selkey;
    unsigned long long prefix;             // radix-select state
    int                hist[256];
    int                kk;
    int                cnt;
};

__device__ __forceinline__ unsigned long long make_key(float s, int i) {
    // score descending, then original index ascending (matches jax top_k + argmax ties)
    return ((unsigned long long)__float_as_uint(s) << 32)
         | (unsigned long long)(0xFFFFFFFFu - (unsigned)i);
}

extern __shared__ unsigned char smem_raw[];

__global__ void __launch_bounds__(NT, 1)
roibbox_kernel(const float* __restrict__ deltas,   // [B, A, 4]
               const float* __restrict__ probs,    // [B, A]
               const float* __restrict__ anchors,  // [A, 4]
               float* __restrict__ out_boxes,      // [B, 1500, 4]
               float* __restrict__ out_scores)     // [B, 1500]
{
    Smem* s = (Smem*)smem_raw;
    const int b    = blockIdx.x;
    const int tid  = threadIdx.x;
    const int warp = tid >> 5;
    const int lane = tid & 31;

    const float* pr = probs + (size_t)b * A_TOTAL;

    // ---------------- Phase 1: exact 6000th-largest key via byte radix-select ----------------
    if (tid == 0) { s->prefix = 0ULL; s->kk = PRE_TOPN; }
    __syncthreads();

    for (int pass = 0; pass < 8; ++pass) {
        const int shift = 56 - 8 * pass;
        if (tid < 256) s->hist[tid] = 0;
        __syncthreads();

        const unsigned long long pref = s->prefix;
        for (int i = tid; i < A_TOTAL; i += NT) {
            unsigned long long k = make_key(pr[i], i);
            bool match = (pass == 0) || ((k >> (shift + 8)) == pref);
            if (match) atomicAdd(&s->hist[(int)((k >> shift) & 255ULL)], 1);
        }
        __syncthreads();

        if (tid == 0) {
            int kk = s->kk;
            int cum = 0, bsel = 0;
            for (int bb = 255; bb >= 0; --bb) {
                int h = s->hist[bb];
                if (cum + h >= kk) { bsel = bb; s->kk = kk - cum; break; }
                cum += h;
            }
            s->prefix = (pref << 8) | (unsigned long long)bsel;
        }
        __syncthreads();
    }
    const unsigned long long thresh = s->prefix;  // exact 6000th-largest key (keys distinct)

    // ---------------- Phase 2: compact top-6000 + decode boxes into SMEM staging -------------
    if (tid == 0) s->cnt = 0;
    __syncthreads();

    const float4* anc4 = (const float4*)anchors;
    const float4* del4 = (const float4*)(deltas + (size_t)b * A_TOTAL * 4);

    for (int i = tid; i < A_TOTAL; i += NT) {
        unsigned long long k = make_key(pr[i], i);
        if (k >= thresh) {
            int p = atomicAdd(&s->cnt, 1);
            float4 a = anc4[i];
            float4 d = del4[i];
            float anc_h = a.z - a.x;
            float anc_w = a.w - a.y;
            float acy   = a.x + 0.5f * anc_h;
            float acx   = a.y + 0.5f * anc_w;
            float h  = expf(d.z * 0.2f) * anc_h;
            float w  = expf(d.w * 0.2f) * anc_w;
            float cy = d.x * 0.1f * anc_h + acy;
            float cx = d.y * 0.1f * anc_w + acx;
            s->cbox[p] = make_float4(cy - 0.5f * h, cx - 0.5f * w,
                                     cy + 0.5f * h, cx + 0.5f * w);
            s->ckey[p] = k;
        }
    }
    __syncthreads();

    // ---------------- Phase 2b: pull candidates into registers (12 per thread) ---------------
    unsigned long long key[NSLOT];
    float4             box[NSLOT];
    #pragma unroll
    for (int k = 0; k < NSLOT; ++k) {
        int idx = k * NT + tid;
        if (idx < PRE_TOPN) { key[k] = s->ckey[idx]; box[k] = s->cbox[idx]; }
        else                { key[k] = 0ULL; box[k] = make_float4(0.f, 0.f, 0.f, 0.f); }
    }

    // prologue: initial local argmax
    unsigned long long bk = 0ULL;
    float4             bb = box[0];
    #pragma unroll
    for (int k = 0; k < NSLOT; ++k) {
        if (key[k] > bk) { bk = key[k]; bb = box[k]; }
    }

    // ---------------- Phase 3: greedy NMS, fused suppress+argmax, register-resident ----------
    float* ob = out_boxes  + (size_t)b * POST_TOPN * 4;
    float* os = out_scores + (size_t)b * POST_TOPN;

    int t = 0;
    for (; t < POST_TOPN; ++t) {
        // warp reduce (key, box)
        #pragma unroll
        for (int off = 16; off; off >>= 1) {
            unsigned long long ok = __shfl_down_sync(0xffffffffu, bk, off);
            float oy = __shfl_down_sync(0xffffffffu, bb.x, off);
            float ox = __shfl_down_sync(0xffffffffu, bb.y, off);
            float oz = __shfl_down_sync(0xffffffffu, bb.z, off);
            float ow = __shfl_down_sync(0xffffffffu, bb.w, off);
            if (ok > bk) { bk = ok; bb = make_float4(oy, ox, oz, ow); }
        }
        if (lane == 0) { s->wkey[warp] = bk; s->wbox[warp] = bb; }
        __syncthreads();

        if (warp == 0) {
            bk = (lane < NWARP) ? s->wkey[lane] : 0ULL;
            bb = (lane < NWARP) ? s->wbox[lane] : make_float4(0.f, 0.f, 0.f, 0.f);
            #pragma unroll
            for (int off = 8; off; off >>= 1) {
                unsigned long long ok = __shfl_down_sync(0xffffffffu, bk, off);
                float oy = __shfl_down_sync(0xffffffffu, bb.x, off);
                float ox = __shfl_down_sync(0xffffffffu, bb.y, off);
                float oz = __shfl_down_sync(0xffffffffu, bb.z, off);
                float ow = __shfl_down_sync(0xffffffffu, bb.w, off);
                if (ok > bk) { bk = ok; bb = make_float4(oy, ox, oz, ow); }
            }
            if (lane == 0) {
                s->selkey = bk;
                s->selbox = bb;
                if (bk != 0ULL) {
                    float4 ocl;
                    ocl.x = fminf(fmaxf(bb.x, 0.0f), 1.0f);
                    ocl.y = fminf(fmaxf(bb.y, 0.0f), 1.0f);
                    ocl.z = fminf(fmaxf(bb.z, 0.0f), 1.0f);
                    ocl.w = fminf(fmaxf(bb.w, 0.0f), 1.0f);
                    ((float4*)ob)[t] = ocl;
                    os[t] = __uint_as_float((unsigned)(bk >> 32));
                }
            }
        }
        __syncthreads();

        const unsigned long long sk = s->selkey;
        if (sk == 0ULL) break;  // no active candidates remain
        const float4 sb = s->selbox;
        const float area_s = (sb.z - sb.x) * (sb.w - sb.y);

        // fused: suppress against sb AND compute next local argmax (selected box
        // self-suppresses via IoU == 1)
        bk = 0ULL;
        bb = box[0];
        #pragma unroll
        for (int k = 0; k < NSLOT; ++k) {
            float4 c4 = box[k];
            float y1 = fmaxf(sb.x, c4.x);
            float x1 = fmaxf(sb.y, c4.y);
            float y2 = fminf(sb.z, c4.z);
            float x2 = fminf(sb.w, c4.w);
            float inter  = fmaxf(y2 - y1, 0.0f) * fmaxf(x2 - x1, 0.0f);
            float area_b = (c4.z - c4.x) * (c4.w - c4.y);
            float iou = inter / (area_s + area_b - inter + 1e-9f);
            unsigned long long kk2 = key[k];
            if (iou > IOU_THR) kk2 = 0ULL;
            key[k] = kk2;
            if (kk2 > bk) { bk = kk2; bb = c4; }
        }
    }

    // zero-fill remaining slots (reference emits zeros once candidates are exhausted)
    for (int idx = t * 4 + tid; idx < POST_TOPN * 4; idx += NT) ob[idx] = 0.0f;
    for (int idx = t + tid;     idx < POST_TOPN;     idx += NT) os[idx] = 0.0f;
}

extern "C" void kernel_launch(void* const* d_in, const int* in_sizes, int n_in,
                              void* d_out, int out_size) {
    const float* deltas  = (const float*)d_in[0];   // [64,31,31,36] f32
    const float* probs   = (const float*)d_in[1];   // [64,31,31,9]  f32
    // d_in[2]: gt_labels int64 — unused
    const float* anchors = (const float*)d_in[3];   // [8649,4] f32

    float* out_boxes  = (float*)d_out;                                   // [64,1500,4]
    float* out_scores = (float*)d_out + (size_t)BATCH_N * POST_TOPN * 4; // [64,1500]

    const size_t smem_bytes = sizeof(Smem);
    cudaFuncSetAttribute(roibbox_kernel,
                         cudaFuncAttributeMaxDynamicSharedMemorySize,
                         (int)smem_bytes);

    roibbox_kernel<<<BATCH_N, NT, smem_bytes>>>(
        deltas, probs, anchors, out_boxes, out_scores);
}

// round 7
// speedup vs baseline: 5.4461x; 3.8712x over previous
#include <cuda_runtime.h>
#include <cstdint>

#define A_TOTAL   8649        // 31*31*9
#define BATCH_N   64
#define PRE_TOPN  6000
#define POST_TOPN 1500
#define NT        512
#define NSLOT     12          // ceil(6000/512)
#define NWARP     16
#define NBUCKET   4096
#define RINF      0x7FFFFFFFu

struct Smem {
    float4             cbox[PRE_TOPN];     // decoded candidate boxes (staging order)
    unsigned long long ckey[PRE_TOPN];     // (score_bits<<32)|(~idx)
    int                inv[PRE_TOPN];      // rank -> staging index
    int                bidx[PRE_TOPN];     // bucket-scatter list / scan scratch
    int                hist[NBUCKET];      // phase-1 radix hist (256) + bucket hist
    unsigned           wmin[2][NWARP];     // per-warp min rank, double-buffered
    unsigned long long prefix;             // radix-select state
    int                kk;
    int                cnt;
};

__device__ __forceinline__ unsigned long long make_key(float s, int i) {
    // score descending, then original index ascending (matches jax top_k + argmax ties)
    return ((unsigned long long)__float_as_uint(s) << 32)
         | (unsigned long long)(0xFFFFFFFFu - (unsigned)i);
}

__device__ __forceinline__ int bucket_of(unsigned long long key) {
    // scores are uniform in [0,1): value-monotone bucket (monotone mul + trunc)
    float sc = __uint_as_float((unsigned)(key >> 32));
    int b = (int)(sc * (float)NBUCKET);
    return b > (NBUCKET - 1) ? (NBUCKET - 1) : b;
}

extern __shared__ unsigned char smem_raw[];

__global__ void __launch_bounds__(NT, 1)
roibbox_kernel(const float* __restrict__ deltas,   // [B, A, 4]
               const float* __restrict__ probs,    // [B, A]
               const float* __restrict__ anchors,  // [A, 4]
               float* __restrict__ out_boxes,      // [B, 1500, 4]
               float* __restrict__ out_scores)     // [B, 1500]
{
    Smem* s = (Smem*)smem_raw;
    const int b    = blockIdx.x;
    const int tid  = threadIdx.x;

    const float* pr = probs + (size_t)b * A_TOTAL;

    // ---------------- Phase 1: exact 6000th-largest key via byte radix-select ----------------
    if (tid == 0) { s->prefix = 0ULL; s->kk = PRE_TOPN; }
    __syncthreads();

    for (int pass = 0; pass < 8; ++pass) {
        const int shift = 56 - 8 * pass;
        if (tid < 256) s->hist[tid] = 0;
        __syncthreads();

        const unsigned long long pref = s->prefix;
        for (int i = tid; i < A_TOTAL; i += NT) {
            unsigned long long k = make_key(pr[i], i);
            bool match = (pass == 0) || ((k >> (shift + 8)) == pref);
            if (match) atomicAdd(&s->hist[(int)((k >> shift) & 255ULL)], 1);
        }
        __syncthreads();

        if (tid == 0) {
            int kk = s->kk;
            int cum = 0, bsel = 0;
            for (int bb = 255; bb >= 0; --bb) {
                int h = s->hist[bb];
                if (cum + h >= kk) { bsel = bb; s->kk = kk - cum; break; }
                cum += h;
            }
            s->prefix = (pref << 8) | (unsigned long long)bsel;
        }
        __syncthreads();
    }
    const unsigned long long thresh = s->prefix;  // exact 6000th-largest key (keys distinct)

    // ---------------- Phase 2: compact top-6000 + decode boxes into SMEM ----------------------
    if (tid == 0) s->cnt = 0;
    __syncthreads();

    const float4* anc4 = (const float4*)anchors;
    const float4* del4 = (const float4*)(deltas + (size_t)b * A_TOTAL * 4);

    for (int i = tid; i < A_TOTAL; i += NT) {
        unsigned long long k = make_key(pr[i], i);
        if (k >= thresh) {
            int p = atomicAdd(&s->cnt, 1);
            float4 a = anc4[i];
            float4 d = del4[i];
            float anc_h = a.z - a.x;
            float anc_w = a.w - a.y;
            float acy   = a.x + 0.5f * anc_h;
            float acx   = a.y + 0.5f * anc_w;
            float h  = expf(d.z * 0.2f) * anc_h;
            float w  = expf(d.w * 0.2f) * anc_w;
            float cy = d.x * 0.1f * anc_h + acy;
            float cx = d.y * 0.1f * anc_w + acx;
            s->cbox[p] = make_float4(cy - 0.5f * h, cx - 0.5f * w,
                                     cy + 0.5f * h, cx + 0.5f * w);
            s->ckey[p] = k;
        }
    }
    __syncthreads();

    // ---------------- Phase 2b: exact rank of every candidate (desc key order) ----------------
    // bucket histogram
    {
        const int CPT = NBUCKET / NT;  // 8
        const int base = tid * CPT;
        #pragma unroll
        for (int j = 0; j < CPT; ++j) s->hist[base + j] = 0;
        __syncthreads();

        for (int i = tid; i < PRE_TOPN; i += NT)
            atomicAdd(&s->hist[bucket_of(s->ckey[i])], 1);
        __syncthreads();

        // exclusive prefix sum over 4096 buckets (hist -> starts)
        int sum = 0;
        #pragma unroll
        for (int j = 0; j < CPT; ++j) {
            int v = s->hist[base + j];
            s->hist[base + j] = sum;
            sum += v;
        }
        s->bidx[tid] = sum;                 // per-thread totals (scratch)
        __syncthreads();
        if (tid == 0) {
            int run = 0;
            for (int i = 0; i < NT; ++i) { int v = s->bidx[i]; s->bidx[i] = run; run += v; }
        }
        __syncthreads();
        const int off = s->bidx[tid];
        #pragma unroll
        for (int j = 0; j < CPT; ++j) s->hist[base + j] += off;
        __syncthreads();

        // scatter candidate indices by bucket (arbitrary order within bucket)
        for (int i = tid; i < PRE_TOPN; i += NT) {
            int bb = bucket_of(s->ckey[i]);
            int p  = atomicAdd(&s->hist[bb], 1);     // hist[b] becomes end-of-bucket
            s->bidx[p] = i;
        }
        __syncthreads();

        // exact rank: bucket start (= hist[b-1] after scatter) + #larger keys in bucket.
        // Buckets descend in key as b grows, so rank = (#cands in buckets > b) + within.
        // hist holds ascending-bucket ends; descending rank = PRE_TOPN - end + within-larger.
        for (int i = tid; i < PRE_TOPN; i += NT) {
            unsigned long long k = s->ckey[i];
            int bb = bucket_of(k);
            int lo = (bb == 0) ? 0 : s->hist[bb - 1];
            int hi = s->hist[bb];
            int larger = 0;
            for (int j = lo; j < hi; ++j)
                larger += (s->ckey[s->bidx[j]] > k) ? 1 : 0;
            int rank = (PRE_TOPN - hi) + larger;     // higher bucket => smaller rank
            s->inv[rank] = i;
        }
        __syncthreads();
    }

    // ---------------- Phase 2c: register-resident candidates in rank order --------------------
    float4 box[NSLOT];
    float  areab[NSLOT];
    unsigned mask = 0;
    #pragma unroll
    for (int k = 0; k < NSLOT; ++k) {
        int r = k * NT + tid;
        if (r < PRE_TOPN) {
            float4 c = s->cbox[s->inv[r]];
            box[k] = c;
            areab[k] = (c.z - c.x) * (c.w - c.y);
            mask |= (1u << k);
        } else {
            box[k] = make_float4(0.f, 0.f, 0.f, 0.f);
            areab[k] = 0.f;
        }
    }

    // ---------------- Phase 3: greedy NMS — min-live-rank picks, bitmask suppression ----------
    float* ob = out_boxes  + (size_t)b * POST_TOPN * 4;
    float* os = out_scores + (size_t)b * POST_TOPN;

    unsigned r_local = (unsigned)tid;   // slot 0 is live for every thread initially
    int t = 0;
    while (true) {
        unsigned wr = __reduce_min_sync(0xFFFFFFFFu, r_local);
        if ((tid & 31) == 0) s->wmin[t & 1][tid >> 5] = wr;
        __syncthreads();

        unsigned rsel = RINF;
        #pragma unroll
        for (int i = 0; i < NWARP; ++i) rsel = min(rsel, s->wmin[t & 1][i]);
        if (rsel == RINF) break;                     // uniform: no live candidates

        const int sidx = s->inv[rsel];
        const float4 sb = s->cbox[sidx];

        if (tid == 0) {
            float4 o;
            o.x = fminf(fmaxf(sb.x, 0.0f), 1.0f);
            o.y = fminf(fmaxf(sb.y, 0.0f), 1.0f);
            o.z = fminf(fmaxf(sb.z, 0.0f), 1.0f);
            o.w = fminf(fmaxf(sb.w, 0.0f), 1.0f);
            ((float4*)ob)[t] = o;
            os[t] = __uint_as_float((unsigned)(s->ckey[sidx] >> 32));
        }
        ++t;
        if (t == POST_TOPN) break;

        const float area_s = (sb.z - sb.x) * (sb.w - sb.y);
        const unsigned mask0 = mask;
        bool anyNear = false;

        #pragma unroll
        for (int k = 0; k < NSLOT; ++k) {
            float4 c = box[k];
            float y1 = fmaxf(sb.x, c.x);
            float x1 = fmaxf(sb.y, c.y);
            float y2 = fminf(sb.z, c.z);
            float x2 = fminf(sb.w, c.w);
            float inter = fmaxf(y2 - y1, 0.0f) * fmaxf(x2 - x1, 0.0f);
            float d = ((area_s + areab[k]) - inter) + 1e-9f;     // reference assoc order
            float margin = fmaf(-0.7f, d, inter);
            if (margin > 0.0f) mask &= ~(1u << k);
            anyNear = anyNear | (fabsf(margin) <= 1e-5f * d);
        }

        if (anyNear) {   // rare: redo all 12 with the exact reference expression
            mask = mask0;
            #pragma unroll
            for (int k = 0; k < NSLOT; ++k) {
                float4 c = box[k];
                float y1 = fmaxf(sb.x, c.x);
                float x1 = fmaxf(sb.y, c.y);
                float y2 = fminf(sb.z, c.z);
                float x2 = fminf(sb.w, c.w);
                float inter = fmaxf(y2 - y1, 0.0f) * fmaxf(x2 - x1, 0.0f);
                float d = ((area_s + areab[k]) - inter) + 1e-9f;
                float iou = inter / d;
                if (iou > 0.7f) mask &= ~(1u << k);
            }
        }

        r_local = mask ? (unsigned)((__ffs((int)mask) - 1) * NT + tid) : RINF;
    }

    // zero-fill remaining slots (reference emits zeros once candidates are exhausted)
    for (int i = t * 4 + tid; i < POST_TOPN * 4; i += NT) ob[i] = 0.0f;
    for (int i = t + tid;     i < POST_TOPN;     i += NT) os[i] = 0.0f;
}

extern "C" void kernel_launch(void* const* d_in, const int* in_sizes, int n_in,
                              void* d_out, int out_size) {
    const float* deltas  = (const float*)d_in[0];   // [64,31,31,36] f32
    const float* probs   = (const float*)d_in[1];   // [64,31,31,9]  f32
    // d_in[2]: gt_labels int64 — unused
    const float* anchors = (const float*)d_in[3];   // [8649,4] f32

    float* out_boxes  = (float*)d_out;                                   // [64,1500,4]
    float* out_scores = (float*)d_out + (size_t)BATCH_N * POST_TOPN * 4; // [64,1500]

    const size_t smem_bytes = sizeof(Smem);
    cudaFuncSetAttribute(roibbox_kernel,
                         cudaFuncAttributeMaxDynamicSharedMemorySize,
                         (int)smem_bytes);

    roibbox_kernel<<<BATCH_N, NT, smem_bytes>>>(
        deltas, probs, anchors, out_boxes, out_scores);
}

// round 8
// speedup vs baseline: 7.4246x; 1.3633x over previous
#include <cuda_runtime.h>
#include <cstdint>

#define A_TOTAL   8649        // 31*31*9
#define BATCH_N   64
#define PRE_TOPN  6000
#define POST_TOPN 1500
#define NT        512
#define NSLOT     12          // ceil(6000/512)
#define NWARP     16
#define NBUCKET   4096
#define RINF      0x7FFFFFFFu
#define EPOCH     96          // steps between live-set compactions

struct Smem {
    float4             cbox[PRE_TOPN];     // decoded candidate boxes (staging order)
    unsigned long long ckey[PRE_TOPN];     // (score_bits<<32)|(~idx)
    int                inv[PRE_TOPN];      // position -> staging index (buffer A)
    int                bidx[PRE_TOPN];     // phase-2b scratch, then buffer B
    int                hist[NBUCKET];      // radix hist / bucket hist / compaction prefix
    unsigned           wmin[2][NWARP];     // per-warp min rank, double-buffered by step parity
    unsigned long long prefix;             // radix-select state
    int                kk;
    int                cnt;
};

__device__ __forceinline__ unsigned long long make_key(float s, int i) {
    // score descending, then original index ascending (matches jax top_k + argmax ties)
    return ((unsigned long long)__float_as_uint(s) << 32)
         | (unsigned long long)(0xFFFFFFFFu - (unsigned)i);
}

__device__ __forceinline__ int bucket_of(unsigned long long key) {
    float sc = __uint_as_float((unsigned)(key >> 32));
    int b = (int)(sc * (float)NBUCKET);
    return b > (NBUCKET - 1) ? (NBUCKET - 1) : b;
}

// One epoch of greedy NMS with a compile-time live-slot count NS.
// Returns updated pick count t; sets done when candidates exhaust or POST reached.
// Decisions are bit-identical to the reference: fma fast path with exact-div
// fallback inside a 1e-5 relative guard band.
template<int NS>
__device__ __forceinline__ int run_epoch(
    Smem* __restrict__ s, const int* __restrict__ invCur,
    float4 (&box)[NSLOT], float (&areab)[NSLOT], unsigned &mask,
    int t, int tEnd, float* __restrict__ ob, float* __restrict__ os,
    int tid, int lane, int warp, bool &done)
{
    unsigned r_local = mask ? (unsigned)((__ffs((int)mask) - 1) * NT + tid) : RINF;
    while (true) {
        unsigned wr = __reduce_min_sync(0xFFFFFFFFu, r_local);
        if (lane == 0) s->wmin[t & 1][warp] = wr;
        __syncthreads();

        // butterfly min over the 16 per-warp minima (all threads, convergent)
        unsigned rsel = s->wmin[t & 1][lane & 15];
        #pragma unroll
        for (int off = 8; off; off >>= 1)
            rsel = min(rsel, __shfl_xor_sync(0xFFFFFFFFu, rsel, off));

        if (rsel == RINF) { done = true; return t; }

        const int sidx = invCur[rsel];
        const float4 sb = s->cbox[sidx];

        if (tid == 0) {
            float4 o;
            o.x = fminf(fmaxf(sb.x, 0.0f), 1.0f);
            o.y = fminf(fmaxf(sb.y, 0.0f), 1.0f);
            o.z = fminf(fmaxf(sb.z, 0.0f), 1.0f);
            o.w = fminf(fmaxf(sb.w, 0.0f), 1.0f);
            ((float4*)ob)[t] = o;
            os[t] = __uint_as_float((unsigned)(s->ckey[sidx] >> 32));
        }
        ++t;
        if (t == POST_TOPN) { done = true; return t; }

        const float area_s = (sb.z - sb.x) * (sb.w - sb.y);
        const unsigned mask0 = mask;
        bool anyNear = false;

        #pragma unroll
        for (int k = 0; k < NS; ++k) {
            float4 c = box[k];
            float y1 = fmaxf(sb.x, c.x);
            float x1 = fmaxf(sb.y, c.y);
            float y2 = fminf(sb.z, c.z);
            float x2 = fminf(sb.w, c.w);
            float inter = fmaxf(y2 - y1, 0.0f) * fmaxf(x2 - x1, 0.0f);
            float d = ((area_s + areab[k]) - inter) + 1e-9f;   // reference assoc order
            float margin = fmaf(-0.7f, d, inter);
            if (margin > 0.0f) mask &= ~(1u << k);
            anyNear = anyNear | (fabsf(margin) <= 1e-5f * d);
        }

        if (anyNear) {   // rare: redo with the exact reference expression
            mask = mask0;
            #pragma unroll
            for (int k = 0; k < NS; ++k) {
                float4 c = box[k];
                float y1 = fmaxf(sb.x, c.x);
                float x1 = fmaxf(sb.y, c.y);
                float y2 = fminf(sb.z, c.z);
                float x2 = fminf(sb.w, c.w);
                float inter = fmaxf(y2 - y1, 0.0f) * fmaxf(x2 - x1, 0.0f);
                float d = ((area_s + areab[k]) - inter) + 1e-9f;
                float iou = inter / d;
                if (iou > 0.7f) mask &= ~(1u << k);
            }
        }

        r_local = mask ? (unsigned)((__ffs((int)mask) - 1) * NT + tid) : RINF;
        if (t == tEnd) return t;   // epoch boundary AFTER suppression for this pick
    }
}

extern __shared__ unsigned char smem_raw[];

__global__ void __launch_bounds__(NT, 1)
roibbox_kernel(const float* __restrict__ deltas,   // [B, A, 4]
               const float* __restrict__ probs,    // [B, A]
               const float* __restrict__ anchors,  // [A, 4]
               float* __restrict__ out_boxes,      // [B, 1500, 4]
               float* __restrict__ out_scores)     // [B, 1500]
{
    Smem* s = (Smem*)smem_raw;
    const int b    = blockIdx.x;
    const int tid  = threadIdx.x;
    const int warp = tid >> 5;
    const int lane = tid & 31;

    const float* pr = probs + (size_t)b * A_TOTAL;

    // ---------------- Phase 1: exact 6000th-largest key via byte radix-select ----------------
    if (tid == 0) { s->prefix = 0ULL; s->kk = PRE_TOPN; }
    __syncthreads();

    for (int pass = 0; pass < 8; ++pass) {
        const int shift = 56 - 8 * pass;
        if (tid < 256) s->hist[tid] = 0;
        __syncthreads();

        const unsigned long long pref = s->prefix;
        for (int i = tid; i < A_TOTAL; i += NT) {
            unsigned long long k = make_key(pr[i], i);
            bool match = (pass == 0) || ((k >> (shift + 8)) == pref);
            if (match) atomicAdd(&s->hist[(int)((k >> shift) & 255ULL)], 1);
        }
        __syncthreads();

        if (tid == 0) {
            int kk = s->kk;
            int cum = 0, bsel = 0;
            for (int bb = 255; bb >= 0; --bb) {
                int h = s->hist[bb];
                if (cum + h >= kk) { bsel = bb; s->kk = kk - cum; break; }
                cum += h;
            }
            s->prefix = (pref << 8) | (unsigned long long)bsel;
        }
        __syncthreads();
    }
    const unsigned long long thresh = s->prefix;  // exact 6000th-largest key (keys distinct)

    // ---------------- Phase 2: compact top-6000 + decode boxes into SMEM ----------------------
    if (tid == 0) s->cnt = 0;
    __syncthreads();

    const float4* anc4 = (const float4*)anchors;
    const float4* del4 = (const float4*)(deltas + (size_t)b * A_TOTAL * 4);

    for (int i = tid; i < A_TOTAL; i += NT) {
        unsigned long long k = make_key(pr[i], i);
        if (k >= thresh) {
            int p = atomicAdd(&s->cnt, 1);
            float4 a = anc4[i];
            float4 d = del4[i];
            float anc_h = a.z - a.x;
            float anc_w = a.w - a.y;
            float acy   = a.x + 0.5f * anc_h;
            float acx   = a.y + 0.5f * anc_w;
            float h  = expf(d.z * 0.2f) * anc_h;
            float w  = expf(d.w * 0.2f) * anc_w;
            float cy = d.x * 0.1f * anc_h + acy;
            float cx = d.y * 0.1f * anc_w + acx;
            s->cbox[p] = make_float4(cy - 0.5f * h, cx - 0.5f * w,
                                     cy + 0.5f * h, cx + 0.5f * w);
            s->ckey[p] = k;
        }
    }
    __syncthreads();

    // ---------------- Phase 2b: exact rank of every candidate (desc key order) ----------------
    {
        const int CPT = NBUCKET / NT;  // 8
        const int base = tid * CPT;
        #pragma unroll
        for (int j = 0; j < CPT; ++j) s->hist[base + j] = 0;
        __syncthreads();

        for (int i = tid; i < PRE_TOPN; i += NT)
            atomicAdd(&s->hist[bucket_of(s->ckey[i])], 1);
        __syncthreads();

        int sum = 0;
        #pragma unroll
        for (int j = 0; j < CPT; ++j) {
            int v = s->hist[base + j];
            s->hist[base + j] = sum;
            sum += v;
        }
        s->bidx[tid] = sum;
        __syncthreads();
        if (tid == 0) {
            int run = 0;
            for (int i = 0; i < NT; ++i) { int v = s->bidx[i]; s->bidx[i] = run; run += v; }
        }
        __syncthreads();
        const int off = s->bidx[tid];
        #pragma unroll
        for (int j = 0; j < CPT; ++j) s->hist[base + j] += off;
        __syncthreads();

        for (int i = tid; i < PRE_TOPN; i += NT) {
            int bb = bucket_of(s->ckey[i]);
            int p  = atomicAdd(&s->hist[bb], 1);     // hist[b] becomes end-of-bucket
            s->bidx[p] = i;
        }
        __syncthreads();

        for (int i = tid; i < PRE_TOPN; i += NT) {
            unsigned long long k = s->ckey[i];
            int bb = bucket_of(k);
            int lo = (bb == 0) ? 0 : s->hist[bb - 1];
            int hi = s->hist[bb];
            int larger = 0;
            for (int j = lo; j < hi; ++j)
                larger += (s->ckey[s->bidx[j]] > k) ? 1 : 0;
            int rank = (PRE_TOPN - hi) + larger;     // higher bucket => smaller rank
            s->inv[rank] = i;
        }
        __syncthreads();
    }

    // ---------------- Phase 2c: register-resident candidates in rank order --------------------
    float4 box[NSLOT];
    float  areab[NSLOT];
    unsigned mask = 0;
    #pragma unroll
    for (int k = 0; k < NSLOT; ++k) {
        int r = k * NT + tid;
        if (r < PRE_TOPN) {
            float4 c = s->cbox[s->inv[r]];
            box[k] = c;
            areab[k] = (c.z - c.x) * (c.w - c.y);
            mask |= (1u << k);
        } else {
            box[k] = make_float4(0.f, 0.f, 0.f, 0.f);
            areab[k] = 0.f;
        }
    }

    // ---------------- Phase 3: epoch loop — templated NMS + periodic compaction ---------------
    float* ob = out_boxes  + (size_t)b * POST_TOPN * 4;
    float* os = out_scores + (size_t)b * POST_TOPN;

    int t = 0, ns = 12, useB = 0;
    bool done = false;
    const unsigned fullm = 0xFFFFFFFFu;
    const unsigned lml = (1u << lane) - 1u;

    while (!done) {
        const int tEnd = (t + EPOCH < POST_TOPN) ? (t + EPOCH) : POST_TOPN;
        const int* invCur = useB ? s->bidx : s->inv;

        switch (ns) {
            case 12: t = run_epoch<12>(s, invCur, box, areab, mask, t, tEnd, ob, os, tid, lane, warp, done); break;
            case  8: t = run_epoch< 8>(s, invCur, box, areab, mask, t, tEnd, ob, os, tid, lane, warp, done); break;
            case  6: t = run_epoch< 6>(s, invCur, box, areab, mask, t, tEnd, ob, os, tid, lane, warp, done); break;
            case  4: t = run_epoch< 4>(s, invCur, box, areab, mask, t, tEnd, ob, os, tid, lane, warp, done); break;
            case  2: t = run_epoch< 2>(s, invCur, box, areab, mask, t, tEnd, ob, os, tid, lane, warp, done); break;
            default: t = run_epoch< 1>(s, invCur, box, areab, mask, t, tEnd, ob, os, tid, lane, warp, done); break;
        }
        if (done) break;

        // ---- compaction: dense re-pack of live candidates, rank order preserved ----
        int* invNext = useB ? s->inv : s->bidx;

        #pragma unroll
        for (int k = 0; k < NSLOT; ++k) {
            unsigned bal = __ballot_sync(fullm, (mask >> k) & 1u);
            if (lane == 0) s->hist[k * NWARP + warp] = __popc(bal);
        }
        __syncthreads();
        if (tid == 0) {
            int run = 0;
            for (int i = 0; i < NSLOT * NWARP; ++i) { int v = s->hist[i]; s->hist[i] = run; run += v; }
            s->cnt = run;
        }
        __syncthreads();
        const int live = s->cnt;

        #pragma unroll
        for (int k = 0; k < NSLOT; ++k) {
            unsigned bit = (mask >> k) & 1u;
            unsigned bal = __ballot_sync(fullm, bit);
            if (bit) {
                int pos = s->hist[k * NWARP + warp] + __popc(bal & lml);
                invNext[pos] = invCur[k * NT + tid];
            }
        }
        __syncthreads();

        const int c = (live + NT - 1) / NT;
        ns = (c > 8) ? 12 : (c > 6) ? 8 : (c > 4) ? 6 : (c > 2) ? 4 : (c > 1) ? 2 : 1;
        mask = 0;
        #pragma unroll
        for (int k = 0; k < NSLOT; ++k) {
            int idx = k * NT + tid;
            if (k < ns && idx < live) {
                float4 cc = s->cbox[invNext[idx]];
                box[k] = cc;
                areab[k] = (cc.z - cc.x) * (cc.w - cc.y);
                mask |= (1u << k);
            }
        }
        useB ^= 1;
    }

    // zero-fill remaining slots (reference emits zeros once candidates are exhausted)
    for (int i = t * 4 + tid; i < POST_TOPN * 4; i += NT) ob[i] = 0.0f;
    for (int i = t + tid;     i < POST_TOPN;     i += NT) os[i] = 0.0f;
}

extern "C" void kernel_launch(void* const* d_in, const int* in_sizes, int n_in,
                              void* d_out, int out_size) {
    const float* deltas  = (const float*)d_in[0];   // [64,31,31,36] f32
    const float* probs   = (const float*)d_in[1];   // [64,31,31,9]  f32
    // d_in[2]: gt_labels int64 — unused
    const float* anchors = (const float*)d_in[3];   // [8649,4] f32

    float* out_boxes  = (float*)d_out;                                   // [64,1500,4]
    float* out_scores = (float*)d_out + (size_t)BATCH_N * POST_TOPN * 4; // [64,1500]

    const size_t smem_bytes = sizeof(Smem);
    cudaFuncSetAttribute(roibbox_kernel,
                         cudaFuncAttributeMaxDynamicSharedMemorySize,
                         (int)smem_bytes);

    roibbox_kernel<<<BATCH_N, NT, smem_bytes>>>(
        deltas, probs, anchors, out_boxes, out_scores);
}